// round 4
// baseline (speedup 1.0000x reference)
#include <cuda_runtime.h>
#include <cstdint>

// ---------------------------------------------------------------------------
// TraFixV5: GRU (B*J=5120 seqs, T=128, D=64, H=128) -> GAT(5 nodes) -> MLP ->
// actor heads + critic.
// Inputs (metadata order):
//  0 obs [1024,128,5,64] f32      1 edge_index [2,8] i32
//  2 W_ih [384,64]  3 W_hh [384,128]  4 b_ih [384]  5 b_hh [384]
//  6 gat_W [128,128]  7 att_src [4,32]  8 att_dst [4,32]  9 gat_b [128]
// 10 W1 [128,128] 11 b1 [128] 12 W2 [128,64] 13 b2 [64]
// 14 actor_W [5,64,4] 15 actor_b [5,4] 16 critic_W [64,1] 17 critic_b [1]
// Output: logits [1024,5,4] flattened, then value [1024] => 21504 f32.
// ---------------------------------------------------------------------------

typedef unsigned long long ull;

__device__ __forceinline__ ull dup2(float x) {
    ull r; asm("mov.b64 %0, {%1, %1};" : "=l"(r) : "f"(x)); return r;
}
__device__ __forceinline__ float2 up2(ull v) {
    float2 r; asm("mov.b64 {%0, %1}, %2;" : "=f"(r.x), "=f"(r.y) : "l"(v)); return r;
}
// packed dual fp32 FMA (sm_100+): d.lo = a.lo*b.lo + c.lo ; d.hi likewise
__device__ __forceinline__ ull ffma2(ull a, ull b, ull c) {
    ull d; asm("fma.rn.f32x2 %0, %1, %2, %3;" : "=l"(d) : "l"(a), "l"(b), "l"(c));
    return d;
}

#define BATCH 1024
#define TT    128
#define JJ    5
#define DD    64
#define HH    128
#define G3    384
#define BJ    5120   // BATCH*JJ

// scratch (static __device__ arrays: the allocation-guard-safe path)
__device__ float g_GI[(size_t)BJ * TT * G3];  // gi = x@W_ih^T + b_ih, layout [t][row][c]
__device__ float g_H[BJ * HH];                // final GRU hidden

// ===========================================================================
// K1: GI precompute.  grid (80 row-tiles of 64, 16 t-tiles of 8), 384 threads.
// ===========================================================================
#define K1_THREADS 384
#define K1_SMEM ((64 * 385 + 16 * 64) * 4)

__global__ void __launch_bounds__(K1_THREADS, 2)
k1_gi(const float* __restrict__ obs, const float* __restrict__ W_ih,
      const float* __restrict__ b_ih)
{
    extern __shared__ float sm[];
    float* Wih_s = sm;             // [d][c] padded stride 385 (conflict-free)
    float* xs    = sm + 64 * 385;  // [d][r] 16 rows

    const int tid = threadIdx.x;
    const int c   = tid;

    for (int idx = tid; idx < G3 * DD; idx += K1_THREADS) {
        int cc = idx >> 6, d = idx & 63;
        Wih_s[d * 385 + cc] = W_ih[idx];          // coalesced read, pad-write
    }
    const ull bias2 = dup2(b_ih[c]);
    __syncthreads();

    const int rowbase0 = blockIdx.x * 64;
    const int tbase    = blockIdx.y * 8;

    for (int tt = 0; tt < 8; ++tt) {
        const int t = tbase + tt;
        for (int rc = 0; rc < 4; ++rc) {
            const int rowbase = rowbase0 + rc * 16;
            // stage x tile [16 rows][64 d] as [d][r]
            for (int idx = tid; idx < 16 * 64; idx += K1_THREADS) {
                int r = idx >> 6, d = idx & 63;
                int row = rowbase + r;
                int b = row / 5, j = row - b * 5;
                xs[d * 16 + r] = obs[(((size_t)b * TT + t) * JJ + j) * DD + d];
            }
            __syncthreads();

            ull acc[8];
#pragma unroll
            for (int p = 0; p < 8; ++p) acc[p] = bias2;
#pragma unroll 4
            for (int d = 0; d < 64; ++d) {
                ull w2 = dup2(Wih_s[d * 385 + c]);
#pragma unroll
                for (int p = 0; p < 8; ++p) {
                    ull x2 = *(const ull*)(xs + d * 16 + 2 * p);  // 2 rows packed
                    acc[p] = ffma2(x2, w2, acc[p]);
                }
            }
            float* gout = g_GI + ((size_t)t * BJ + rowbase) * G3 + c;
#pragma unroll
            for (int p = 0; p < 8; ++p) {
                float2 v = up2(acc[p]);
                gout[(size_t)(2 * p) * G3]     = v.x;
                gout[(size_t)(2 * p + 1) * G3] = v.y;
            }
            __syncthreads();
        }
    }
}

// ===========================================================================
// K2: persistent GRU. 128 CTAs x 40 rows. 512 threads = (i in [0,128)) x
// (group g in [0,4), 10 rows each). Thread (i,g) owns gates r,z,n at hidden
// index i for its 10 rows -> no cross-thread gate exchange.
// SMEM: W_hh [c][k] stride 132 (LDS.128, conflict-free) + h as float2 pairs
// [pair][k]. Packed f32x2 FMA over row pairs.
// ===========================================================================
#define K2_THREADS 512
#define K2_CTAS    128
#define ROWS       40
#define WCS        132
#define K2_SMEM    ((G3 * WCS + 20 * HH * 2) * 4)

__global__ void __launch_bounds__(K2_THREADS, 1)
k2_gru(const float* __restrict__ W_hh, const float* __restrict__ b_hh)
{
    extern __shared__ float sm[];
    float* Wc  = sm;             // [384][132]
    float* hsf = sm + G3 * WCS;  // [20 pairs][128 k] float2 flattened

    const int tid = threadIdx.x;
    const int i   = tid & 127;
    const int g   = tid >> 7;
    const int rowbase = blockIdx.x * ROWS;

    for (int idx = tid; idx < G3 * HH; idx += K2_THREADS) {
        int cc = idx >> 7, k = idx & 127;
        Wc[cc * WCS + k] = W_hh[idx];             // coalesced, conflict-free
    }
    for (int idx = tid; idx < 20 * HH * 2; idx += K2_THREADS) hsf[idx] = 0.f;

    const float br = b_hh[i], bz = b_hh[HH + i], bn = b_hh[2 * HH + i];
    __syncthreads();

    const float* Wr = Wc + i * WCS;
    const float* Wz = Wc + (HH + i) * WCS;
    const float* Wn = Wc + (2 * HH + i) * WCS;
    const float* hg = hsf + (g * 5) * HH * 2;     // my group's 5 row-pairs

    for (int t = 0; t < TT; ++t) {
        // prefetch gi for my 10 rows (overlaps with k-loop below)
        const float* gi_t = g_GI + ((size_t)t * BJ + rowbase + g * 10) * G3;
        float gr[10], gz[10], gn[10];
#pragma unroll
        for (int r = 0; r < 10; ++r) {
            const float* p = gi_t + (size_t)r * G3;
            gr[r] = p[i]; gz[r] = p[HH + i]; gn[r] = p[2 * HH + i];
        }

        ull ar[5], az[5], an[5];
#pragma unroll
        for (int p = 0; p < 5; ++p) { ar[p] = dup2(br); az[p] = dup2(bz); an[p] = dup2(bn); }

#pragma unroll 2
        for (int k = 0; k < HH; k += 4) {
            float4 wr4 = *(const float4*)(Wr + k);
            float4 wz4 = *(const float4*)(Wz + k);
            float4 wn4 = *(const float4*)(Wn + k);
#pragma unroll
            for (int kk = 0; kk < 4; ++kk) {
                float wr = ((const float*)&wr4)[kk];
                float wz = ((const float*)&wz4)[kk];
                float wn = ((const float*)&wn4)[kk];
                ull wr2 = dup2(wr), wz2 = dup2(wz), wn2 = dup2(wn);
#pragma unroll
                for (int p = 0; p < 5; ++p) {
                    ull h2 = *(const ull*)(hg + (p * HH + k + kk) * 2);
                    ar[p] = ffma2(h2, wr2, ar[p]);
                    az[p] = ffma2(h2, wz2, az[p]);
                    an[p] = ffma2(h2, wn2, an[p]);
                }
            }
        }

        // gates + state update (rows 2p, 2p+1 of my group)
        float2 hnew[5];
#pragma unroll
        for (int p = 0; p < 5; ++p) {
            float2 ghr = up2(ar[p]), ghz = up2(az[p]), ghn = up2(an[p]);
            float2 hold = *(const float2*)(hsf + ((g * 5 + p) * HH + i) * 2);
            float ra = 1.f / (1.f + __expf(-(gr[2 * p]     + ghr.x)));
            float rb = 1.f / (1.f + __expf(-(gr[2 * p + 1] + ghr.y)));
            float za = 1.f / (1.f + __expf(-(gz[2 * p]     + ghz.x)));
            float zb = 1.f / (1.f + __expf(-(gz[2 * p + 1] + ghz.y)));
            float na = tanhf(gn[2 * p]     + ra * ghn.x);
            float nb = tanhf(gn[2 * p + 1] + rb * ghn.y);
            hnew[p].x = (1.f - za) * na + za * hold.x;
            hnew[p].y = (1.f - zb) * nb + zb * hold.y;
        }
        __syncthreads();   // all k-loop reads of hs complete
#pragma unroll
        for (int p = 0; p < 5; ++p)
            *(float2*)(hsf + ((g * 5 + p) * HH + i) * 2) = hnew[p];
        __syncthreads();   // writes visible before next step's reads
    }

    for (int idx = tid; idx < ROWS * HH; idx += K2_THREADS) {
        int r = idx >> 7, k = idx & 127;
        g_H[(rowbase + r) * HH + k] = hsf[((r >> 1) * HH + k) * 2 + (r & 1)];
    }
}

// ===========================================================================
// K3: GAT + trunk MLP + actor/critic.  256 blocks x 256 threads, 4 batches
// per block; all weights staged in smem once per block.
// ===========================================================================
#define K3_THREADS 256
#define K3_SMEM ((16384 + 16384 + 8192 + 640 * 4 + 320 + 20 + 20 + 100 + 8 + 32) * 4)

__global__ void __launch_bounds__(K3_THREADS, 1)
k3_head(const int* __restrict__ edge,
        const float* __restrict__ gat_W, const float* __restrict__ att_src,
        const float* __restrict__ att_dst, const float* __restrict__ gat_b,
        const float* __restrict__ W1, const float* __restrict__ b1,
        const float* __restrict__ W2, const float* __restrict__ b2,
        const float* __restrict__ actW, const float* __restrict__ actb,
        const float* __restrict__ crW, const float* __restrict__ crb,
        float* __restrict__ out)
{
    extern __shared__ float sm[];
    float* gatW_s = sm;              // 16384  [k][o]
    float* W1_s   = gatW_s + 16384;  // 16384  [o][m]
    float* W2_s   = W1_s + 16384;    // 8192   [m][u]
    float* h_s    = W2_s + 8192;     // 640
    float* xp_s   = h_s + 640;       // 640
    float* g_s    = xp_s + 640;      // 640
    float* t1_s   = g_s + 640;       // 640
    float* t2_s   = t1_s + 640;      // 320
    float* as_s   = t2_s + 320;      // 20
    float* ad_s   = as_s + 20;       // 20
    float* al_s   = ad_s + 20;       // 100  alpha [i][j][head]
    float* red_s  = al_s + 100;      // 8
    int*   adj_s  = (int*)(red_s + 8);

    const int tid = threadIdx.x;

    for (int idx = tid; idx < 16384; idx += K3_THREADS) gatW_s[idx] = gat_W[idx];
    for (int idx = tid; idx < 16384; idx += K3_THREADS) W1_s[idx] = W1[idx];
    for (int idx = tid; idx < 8192;  idx += K3_THREADS) W2_s[idx] = W2[idx];
    if (tid < 25) adj_s[tid] = (tid / 5 == tid % 5) ? 1 : 0;  // self-loops
    __syncthreads();
    if (tid < 8) adj_s[edge[8 + tid] * 5 + edge[tid]] = 1;     // adj[dst][src]
    __syncthreads();

    for (int bb = 0; bb < 4; ++bb) {
        const int batch = blockIdx.x * 4 + bb;

        for (int idx = tid; idx < 640; idx += K3_THREADS)
            h_s[idx] = g_H[batch * 5 * HH + idx];
        __syncthreads();

        // xp = h @ gat_W
        for (int idx = tid; idx < 640; idx += K3_THREADS) {
            int j = idx >> 7, o = idx & 127;
            float a = 0.f;
#pragma unroll 8
            for (int k = 0; k < 128; ++k) a += h_s[j * 128 + k] * gatW_s[k * 128 + o];
            xp_s[idx] = a;
        }
        __syncthreads();

        // attention scores per (j, head)
        if (tid < 20) {
            int j = tid >> 2, h = tid & 3;
            float s1 = 0.f, s2 = 0.f;
            for (int d = 0; d < 32; ++d) {
                float v = xp_s[j * 128 + h * 32 + d];
                s1 += v * att_src[h * 32 + d];
                s2 += v * att_dst[h * 32 + d];
            }
            as_s[tid] = s1; ad_s[tid] = s2;
        }
        __syncthreads();

        // masked leaky-relu softmax over src j per (dst i, head)
        if (tid < 20) {
            int ii = tid >> 2, h = tid & 3;
            float ev[5]; float m = -1e30f;
#pragma unroll
            for (int j = 0; j < 5; ++j) {
                float e = as_s[j * 4 + h] + ad_s[ii * 4 + h];
                e = e > 0.f ? e : 0.2f * e;
                if (!adj_s[ii * 5 + j]) e = -1e30f;
                ev[j] = e; m = fmaxf(m, e);
            }
            float s = 0.f;
#pragma unroll
            for (int j = 0; j < 5; ++j) {
                ev[j] = adj_s[ii * 5 + j] ? __expf(ev[j] - m) : 0.f;
                s += ev[j];
            }
            float inv = 1.f / s;
#pragma unroll
            for (int j = 0; j < 5; ++j) al_s[(ii * 5 + j) * 4 + h] = ev[j] * inv;
        }
        __syncthreads();

        // aggregate: g[i][o] = sum_j alpha[i][j][o/32] * xp[j][o] + gat_b
        for (int idx = tid; idx < 640; idx += K3_THREADS) {
            int ii = idx >> 7, o = idx & 127;
            int h = o >> 5;
            float a = gat_b[o];
#pragma unroll
            for (int j = 0; j < 5; ++j) a += al_s[(ii * 5 + j) * 4 + h] * xp_s[j * 128 + o];
            g_s[idx] = a;
        }
        __syncthreads();

        // t1 = relu(g @ W1 + b1)
        for (int idx = tid; idx < 640; idx += K3_THREADS) {
            int ii = idx >> 7, m2 = idx & 127;
            float a = b1[m2];
#pragma unroll 8
            for (int o = 0; o < 128; ++o) a += g_s[ii * 128 + o] * W1_s[o * 128 + m2];
            t1_s[idx] = fmaxf(a, 0.f);
        }
        __syncthreads();

        // t2 = relu(t1 @ W2 + b2)
        for (int idx = tid; idx < 320; idx += K3_THREADS) {
            int ii = idx >> 6, u = idx & 63;
            float a = b2[u];
#pragma unroll 8
            for (int m2 = 0; m2 < 128; ++m2) a += t1_s[ii * 128 + m2] * W2_s[m2 * 64 + u];
            t2_s[idx] = fmaxf(a, 0.f);
        }
        __syncthreads();

        // per-junction actor logits
        if (tid < 20) {
            int j = tid >> 2, p = tid & 3;
            float a = actb[j * 4 + p];
            for (int u = 0; u < 64; ++u) a += t2_s[j * 64 + u] * actW[(j * 64 + u) * 4 + p];
            out[batch * 20 + j * 4 + p] = a;
        }

        // critic on junction mean
        float v = 0.f;
        if (tid < 64) {
            float s = t2_s[tid] + t2_s[64 + tid] + t2_s[128 + tid] +
                      t2_s[192 + tid] + t2_s[256 + tid];
            v = s * 0.2f * crW[tid];
        }
        v += __shfl_down_sync(0xffffffffu, v, 16);
        v += __shfl_down_sync(0xffffffffu, v, 8);
        v += __shfl_down_sync(0xffffffffu, v, 4);
        v += __shfl_down_sync(0xffffffffu, v, 2);
        v += __shfl_down_sync(0xffffffffu, v, 1);
        if (tid < 64 && (tid & 31) == 0) red_s[tid >> 5] = v;
        __syncthreads();
        if (tid == 0) out[BATCH * JJ * 4 + batch] = red_s[0] + red_s[1] + crb[0];
        __syncthreads();   // buffers reused by next batch
    }
}

// ===========================================================================
extern "C" void kernel_launch(void* const* d_in, const int* in_sizes, int n_in,
                              void* d_out, int out_size)
{
    const float* obs     = (const float*)d_in[0];
    const int*   edge    = (const int*)  d_in[1];
    const float* W_ih    = (const float*)d_in[2];
    const float* W_hh    = (const float*)d_in[3];
    const float* b_ih    = (const float*)d_in[4];
    const float* b_hh    = (const float*)d_in[5];
    const float* gat_W   = (const float*)d_in[6];
    const float* att_src = (const float*)d_in[7];
    const float* att_dst = (const float*)d_in[8];
    const float* gat_b   = (const float*)d_in[9];
    const float* W1      = (const float*)d_in[10];
    const float* b1      = (const float*)d_in[11];
    const float* W2      = (const float*)d_in[12];
    const float* b2      = (const float*)d_in[13];
    const float* actW    = (const float*)d_in[14];
    const float* actb    = (const float*)d_in[15];
    const float* crW     = (const float*)d_in[16];
    const float* crb     = (const float*)d_in[17];
    float* out = (float*)d_out;

    cudaFuncSetAttribute(k1_gi,   cudaFuncAttributeMaxDynamicSharedMemorySize, K1_SMEM);
    cudaFuncSetAttribute(k2_gru,  cudaFuncAttributeMaxDynamicSharedMemorySize, K2_SMEM);
    cudaFuncSetAttribute(k3_head, cudaFuncAttributeMaxDynamicSharedMemorySize, K3_SMEM);

    k1_gi<<<dim3(80, 16), K1_THREADS, K1_SMEM>>>(obs, W_ih, b_ih);
    k2_gru<<<K2_CTAS, K2_THREADS, K2_SMEM>>>(W_hh, b_hh);
    k3_head<<<256, K3_THREADS, K3_SMEM>>>(edge, gat_W, att_src, att_dst, gat_b,
                                          W1, b1, W2, b2, actW, actb, crW, crb, out);
}

// round 5
// speedup vs baseline: 1.0304x; 1.0304x over previous
#include <cuda_runtime.h>
#include <cstdint>

// ---------------------------------------------------------------------------
// TraFixV5: GRU (B*J=5120 seqs, T=128, D=64, H=128) -> GAT(5 nodes) -> MLP ->
// actor heads + critic.
// Round 4: k-packed f32x2 (no dup2 splats), register-blocked K1 (4x4),
// K2 spread to 148 CTAs x 35 rows with named per-group barriers.
// ---------------------------------------------------------------------------

typedef unsigned long long ull;

__device__ __forceinline__ ull ffma2(ull a, ull b, ull c) {
    ull d; asm("fma.rn.f32x2 %0, %1, %2, %3;" : "=l"(d) : "l"(a), "l"(b), "l"(c));
    return d;
}
__device__ __forceinline__ float2 up2(ull v) {
    float2 r; asm("mov.b64 {%0, %1}, %2;" : "=f"(r.x), "=f"(r.y) : "l"(v)); return r;
}

#define BATCH 1024
#define TT    128
#define JJ    5
#define DD    64
#define HH    128
#define G3    384
#define BJ    5120   // BATCH*JJ
#define PAD_ROWS 64  // over-partition slack for 148x35 = 5180 rows

// scratch (static __device__ arrays: the allocation-guard-safe path)
__device__ float g_GI[((size_t)BJ * TT + PAD_ROWS) * G3];  // [t][row][c]
__device__ float g_H[(BJ + PAD_ROWS) * HH];                // final GRU hidden

// ===========================================================================
// K1: gi = x @ W_ih^T + b_ih.  grid (160 row-tiles of 32, 8 t-chunks of 16),
// 768 threads = 96 col-groups x 8 row-groups; each thread: 4 rows x 4 cols,
// k(=d)-packed f32x2: acc.x sums even d, acc.y odd d; horizontal add at end.
// ===========================================================================
#define K1_THREADS 768
#define DP 68   // smem stride (floats): 17 x 16B, odd -> conflict-free LDS.128
#define K1_SMEM ((G3 * DP + 32 * DP + G3) * 4)

__global__ void __launch_bounds__(K1_THREADS, 1)
k1_gi(const float* __restrict__ obs, const float* __restrict__ W_ih,
      const float* __restrict__ b_ih)
{
    extern __shared__ float sm[];
    float* Ws = sm;                // [c][d] stride DP
    float* xs = sm + G3 * DP;      // [r][d] stride DP, 32 rows
    float* bs = xs + 32 * DP;      // bias [384]

    const int tid = threadIdx.x;
    const int cg  = tid % 96;      // cols cg, cg+96, cg+192, cg+288
    const int rg  = tid / 96;      // 0..7 -> rows 4*rg..4*rg+3
    const int r0  = rg * 4;

    for (int idx = tid; idx < G3 * DD; idx += K1_THREADS) {
        int c = idx >> 6, d = idx & 63;
        Ws[c * DP + d] = W_ih[idx];
    }
    for (int idx = tid; idx < G3; idx += K1_THREADS) bs[idx] = b_ih[idx];
    __syncthreads();

    const int rowbase = blockIdx.x * 32;
    const int tbase   = blockIdx.y * 16;

    for (int tt = 0; tt < 16; ++tt) {
        const int t = tbase + tt;
        // stage x[32 rows][64 d]
        for (int idx = tid; idx < 32 * 64; idx += K1_THREADS) {
            int r = idx >> 6, d = idx & 63;
            int row = rowbase + r;
            int b = row / 5, j = row - b * 5;
            xs[r * DP + d] = obs[(((size_t)b * TT + t) * JJ + j) * DD + d];
        }
        __syncthreads();

        ull acc[4][4];
#pragma unroll
        for (int cc = 0; cc < 4; ++cc)
#pragma unroll
            for (int r = 0; r < 4; ++r) acc[cc][r] = 0ull;

#pragma unroll 2
        for (int d = 0; d < 64; d += 4) {
            ull xlo[4], xhi[4];
#pragma unroll
            for (int r = 0; r < 4; ++r) {
                float4 xv = *(const float4*)(xs + (r0 + r) * DP + d);  // broadcast
                xlo[r] = *(const ull*)&xv;
                xhi[r] = *((const ull*)&xv + 1);
            }
#pragma unroll
            for (int cc = 0; cc < 4; ++cc) {
                float4 wv = *(const float4*)(Ws + (cg + 96 * cc) * DP + d);
                ull wlo = *(const ull*)&wv, whi = *((const ull*)&wv + 1);
#pragma unroll
                for (int r = 0; r < 4; ++r) {
                    acc[cc][r] = ffma2(xlo[r], wlo, acc[cc][r]);
                    acc[cc][r] = ffma2(xhi[r], whi, acc[cc][r]);
                }
            }
        }

        float* gout = g_GI + ((size_t)t * BJ + rowbase + r0) * G3;
#pragma unroll
        for (int cc = 0; cc < 4; ++cc) {
            int c = cg + 96 * cc;
            float bv = bs[c];
#pragma unroll
            for (int r = 0; r < 4; ++r) {
                float2 v = up2(acc[cc][r]);
                gout[(size_t)r * G3 + c] = v.x + v.y + bv;   // lanes coalesced
            }
        }
        __syncthreads();
    }
}

// ===========================================================================
// K2: persistent GRU. 148 CTAs x 35 rows (5180 >= 5120, padded tail).
// 896 threads = 7 groups of 128: thread (i,g) owns gate index i for the 5
// rows of group g. k-packed f32x2, no splats. Named barriers per group (h
// rows are group-exclusive).
// ===========================================================================
#define K2_THREADS 896
#define K2_CTAS    148
#define R_CTA      35
#define WCS        132  // 33 x 16B, odd -> conflict-free strided LDS.128
#define K2_SMEM    ((G3 * WCS + R_CTA * HH) * 4)

__global__ void __launch_bounds__(K2_THREADS, 1)
k2_gru(const float* __restrict__ W_hh, const float* __restrict__ b_hh)
{
    extern __shared__ float sm[];
    float* Wc = sm;             // [384][132]
    float* hs = sm + G3 * WCS;  // [35][128]

    const int tid = threadIdx.x;
    const int i   = tid & 127;
    const int g   = tid >> 7;   // 0..6
    const int rowbase = blockIdx.x * R_CTA;
    const int lr0 = g * 5;      // local row base

    for (int idx = tid; idx < G3 * HH; idx += K2_THREADS) {
        int c = idx >> 7, k = idx & 127;
        Wc[c * WCS + k] = W_hh[idx];
    }
    for (int idx = tid; idx < R_CTA * HH; idx += K2_THREADS) hs[idx] = 0.f;
    __syncthreads();

    const float br = b_hh[i], bz = b_hh[HH + i], bn = b_hh[2 * HH + i];
    const float* Wr = Wc + i * WCS;
    const float* Wz = Wc + (HH + i) * WCS;
    const float* Wn = Wc + (2 * HH + i) * WCS;
    const float* hb = hs + lr0 * HH;

    for (int t = 0; t < TT; ++t) {
        // hoist gi loads: latency hidden under the ~13k-cycle k-loop
        const float* gi = g_GI + ((size_t)t * BJ + rowbase + lr0) * G3;
        float gr[5], gz[5], gn[5];
#pragma unroll
        for (int p = 0; p < 5; ++p) {
            const float* q = gi + (size_t)p * G3;
            gr[p] = __ldg(q + i); gz[p] = __ldg(q + HH + i); gn[p] = __ldg(q + 2 * HH + i);
        }

        ull ar[5], az[5], an[5];
#pragma unroll
        for (int p = 0; p < 5; ++p) { ar[p] = 0ull; az[p] = 0ull; an[p] = 0ull; }

#pragma unroll 2
        for (int k = 0; k < HH; k += 4) {
            float4 w4r = *(const float4*)(Wr + k);
            float4 w4z = *(const float4*)(Wz + k);
            float4 w4n = *(const float4*)(Wn + k);
            ull wrlo = *(const ull*)&w4r, wrhi = *((const ull*)&w4r + 1);
            ull wzlo = *(const ull*)&w4z, wzhi = *((const ull*)&w4z + 1);
            ull wnlo = *(const ull*)&w4n, wnhi = *((const ull*)&w4n + 1);
#pragma unroll
            for (int p = 0; p < 5; ++p) {
                float4 h4 = *(const float4*)(hb + p * HH + k);   // broadcast
                ull hlo = *(const ull*)&h4, hhi = *((const ull*)&h4 + 1);
                ar[p] = ffma2(hlo, wrlo, ar[p]); ar[p] = ffma2(hhi, wrhi, ar[p]);
                az[p] = ffma2(hlo, wzlo, az[p]); az[p] = ffma2(hhi, wzhi, az[p]);
                an[p] = ffma2(hlo, wnlo, an[p]); an[p] = ffma2(hhi, wnhi, an[p]);
            }
        }

        float hnew[5];
#pragma unroll
        for (int p = 0; p < 5; ++p) {
            float2 vr = up2(ar[p]), vz = up2(az[p]), vn = up2(an[p]);
            float ghr = vr.x + vr.y + br;
            float ghz = vz.x + vz.y + bz;
            float ghn = vn.x + vn.y + bn;
            float hold = hs[(lr0 + p) * HH + i];
            float r = 1.f / (1.f + __expf(-(gr[p] + ghr)));
            float z = 1.f / (1.f + __expf(-(gz[p] + ghz)));
            float n = tanhf(gn[p] + r * ghn);
            hnew[p] = (1.f - z) * n + z * hold;
        }
        asm volatile("bar.sync %0, %1;" :: "r"(g + 1), "r"(128) : "memory");
#pragma unroll
        for (int p = 0; p < 5; ++p) hs[(lr0 + p) * HH + i] = hnew[p];
        asm volatile("bar.sync %0, %1;" :: "r"(g + 1), "r"(128) : "memory");
    }

    // final h -> gmem (rows >= 5120 land in the padded tail of g_H)
#pragma unroll
    for (int p = 0; p < 5; ++p)
        g_H[(rowbase + lr0 + p) * HH + i] = hs[(lr0 + p) * HH + i];
}

// ===========================================================================
// K3: GAT + trunk MLP + actor/critic.  256 blocks x 256 threads, 4 batches
// per block; all weights staged in smem once per block.  (unchanged)
// ===========================================================================
#define K3_THREADS 256
#define K3_SMEM ((16384 + 16384 + 8192 + 640 * 4 + 320 + 20 + 20 + 100 + 8 + 32) * 4)

__global__ void __launch_bounds__(K3_THREADS, 1)
k3_head(const int* __restrict__ edge,
        const float* __restrict__ gat_W, const float* __restrict__ att_src,
        const float* __restrict__ att_dst, const float* __restrict__ gat_b,
        const float* __restrict__ W1, const float* __restrict__ b1,
        const float* __restrict__ W2, const float* __restrict__ b2,
        const float* __restrict__ actW, const float* __restrict__ actb,
        const float* __restrict__ crW, const float* __restrict__ crb,
        float* __restrict__ out)
{
    extern __shared__ float sm[];
    float* gatW_s = sm;              // 16384  [k][o]
    float* W1_s   = gatW_s + 16384;  // 16384  [o][m]
    float* W2_s   = W1_s + 16384;    // 8192   [m][u]
    float* h_s    = W2_s + 8192;     // 640
    float* xp_s   = h_s + 640;       // 640
    float* g_s    = xp_s + 640;      // 640
    float* t1_s   = g_s + 640;       // 640
    float* t2_s   = t1_s + 640;      // 320
    float* as_s   = t2_s + 320;      // 20
    float* ad_s   = as_s + 20;       // 20
    float* al_s   = ad_s + 20;       // 100  alpha [i][j][head]
    float* red_s  = al_s + 100;      // 8
    int*   adj_s  = (int*)(red_s + 8);

    const int tid = threadIdx.x;

    for (int idx = tid; idx < 16384; idx += K3_THREADS) gatW_s[idx] = gat_W[idx];
    for (int idx = tid; idx < 16384; idx += K3_THREADS) W1_s[idx] = W1[idx];
    for (int idx = tid; idx < 8192;  idx += K3_THREADS) W2_s[idx] = W2[idx];
    if (tid < 25) adj_s[tid] = (tid / 5 == tid % 5) ? 1 : 0;  // self-loops
    __syncthreads();
    if (tid < 8) adj_s[edge[8 + tid] * 5 + edge[tid]] = 1;     // adj[dst][src]
    __syncthreads();

    for (int bb = 0; bb < 4; ++bb) {
        const int batch = blockIdx.x * 4 + bb;

        for (int idx = tid; idx < 640; idx += K3_THREADS)
            h_s[idx] = g_H[batch * 5 * HH + idx];
        __syncthreads();

        // xp = h @ gat_W
        for (int idx = tid; idx < 640; idx += K3_THREADS) {
            int j = idx >> 7, o = idx & 127;
            float a = 0.f;
#pragma unroll 8
            for (int k = 0; k < 128; ++k) a += h_s[j * 128 + k] * gatW_s[k * 128 + o];
            xp_s[idx] = a;
        }
        __syncthreads();

        // attention scores per (j, head)
        if (tid < 20) {
            int j = tid >> 2, h = tid & 3;
            float s1 = 0.f, s2 = 0.f;
            for (int d = 0; d < 32; ++d) {
                float v = xp_s[j * 128 + h * 32 + d];
                s1 += v * att_src[h * 32 + d];
                s2 += v * att_dst[h * 32 + d];
            }
            as_s[tid] = s1; ad_s[tid] = s2;
        }
        __syncthreads();

        // masked leaky-relu softmax over src j per (dst i, head)
        if (tid < 20) {
            int ii = tid >> 2, h = tid & 3;
            float ev[5]; float m = -1e30f;
#pragma unroll
            for (int j = 0; j < 5; ++j) {
                float e = as_s[j * 4 + h] + ad_s[ii * 4 + h];
                e = e > 0.f ? e : 0.2f * e;
                if (!adj_s[ii * 5 + j]) e = -1e30f;
                ev[j] = e; m = fmaxf(m, e);
            }
            float s = 0.f;
#pragma unroll
            for (int j = 0; j < 5; ++j) {
                ev[j] = adj_s[ii * 5 + j] ? __expf(ev[j] - m) : 0.f;
                s += ev[j];
            }
            float inv = 1.f / s;
#pragma unroll
            for (int j = 0; j < 5; ++j) al_s[(ii * 5 + j) * 4 + h] = ev[j] * inv;
        }
        __syncthreads();

        // aggregate: g[i][o] = sum_j alpha[i][j][o/32] * xp[j][o] + gat_b
        for (int idx = tid; idx < 640; idx += K3_THREADS) {
            int ii = idx >> 7, o = idx & 127;
            int h = o >> 5;
            float a = gat_b[o];
#pragma unroll
            for (int j = 0; j < 5; ++j) a += al_s[(ii * 5 + j) * 4 + h] * xp_s[j * 128 + o];
            g_s[idx] = a;
        }
        __syncthreads();

        // t1 = relu(g @ W1 + b1)
        for (int idx = tid; idx < 640; idx += K3_THREADS) {
            int ii = idx >> 7, m2 = idx & 127;
            float a = b1[m2];
#pragma unroll 8
            for (int o = 0; o < 128; ++o) a += g_s[ii * 128 + o] * W1_s[o * 128 + m2];
            t1_s[idx] = fmaxf(a, 0.f);
        }
        __syncthreads();

        // t2 = relu(t1 @ W2 + b2)
        for (int idx = tid; idx < 320; idx += K3_THREADS) {
            int ii = idx >> 6, u = idx & 63;
            float a = b2[u];
#pragma unroll 8
            for (int m2 = 0; m2 < 128; ++m2) a += t1_s[ii * 128 + m2] * W2_s[m2 * 64 + u];
            t2_s[idx] = fmaxf(a, 0.f);
        }
        __syncthreads();

        // per-junction actor logits
        if (tid < 20) {
            int j = tid >> 2, p = tid & 3;
            float a = actb[j * 4 + p];
            for (int u = 0; u < 64; ++u) a += t2_s[j * 64 + u] * actW[(j * 64 + u) * 4 + p];
            out[batch * 20 + j * 4 + p] = a;
        }

        // critic on junction mean
        float v = 0.f;
        if (tid < 64) {
            float s = t2_s[tid] + t2_s[64 + tid] + t2_s[128 + tid] +
                      t2_s[192 + tid] + t2_s[256 + tid];
            v = s * 0.2f * crW[tid];
        }
        v += __shfl_down_sync(0xffffffffu, v, 16);
        v += __shfl_down_sync(0xffffffffu, v, 8);
        v += __shfl_down_sync(0xffffffffu, v, 4);
        v += __shfl_down_sync(0xffffffffu, v, 2);
        v += __shfl_down_sync(0xffffffffu, v, 1);
        if (tid < 64 && (tid & 31) == 0) red_s[tid >> 5] = v;
        __syncthreads();
        if (tid == 0) out[BATCH * JJ * 4 + batch] = red_s[0] + red_s[1] + crb[0];
        __syncthreads();   // buffers reused by next batch
    }
}

// ===========================================================================
extern "C" void kernel_launch(void* const* d_in, const int* in_sizes, int n_in,
                              void* d_out, int out_size)
{
    const float* obs     = (const float*)d_in[0];
    const int*   edge    = (const int*)  d_in[1];
    const float* W_ih    = (const float*)d_in[2];
    const float* W_hh    = (const float*)d_in[3];
    const float* b_ih    = (const float*)d_in[4];
    const float* b_hh    = (const float*)d_in[5];
    const float* gat_W   = (const float*)d_in[6];
    const float* att_src = (const float*)d_in[7];
    const float* att_dst = (const float*)d_in[8];
    const float* gat_b   = (const float*)d_in[9];
    const float* W1      = (const float*)d_in[10];
    const float* b1      = (const float*)d_in[11];
    const float* W2      = (const float*)d_in[12];
    const float* b2      = (const float*)d_in[13];
    const float* actW    = (const float*)d_in[14];
    const float* actb    = (const float*)d_in[15];
    const float* crW     = (const float*)d_in[16];
    const float* crb     = (const float*)d_in[17];
    float* out = (float*)d_out;

    cudaFuncSetAttribute(k1_gi,   cudaFuncAttributeMaxDynamicSharedMemorySize, K1_SMEM);
    cudaFuncSetAttribute(k2_gru,  cudaFuncAttributeMaxDynamicSharedMemorySize, K2_SMEM);
    cudaFuncSetAttribute(k3_head, cudaFuncAttributeMaxDynamicSharedMemorySize, K3_SMEM);

    k1_gi<<<dim3(160, 8), K1_THREADS, K1_SMEM>>>(obs, W_ih, b_ih);
    k2_gru<<<K2_CTAS, K2_THREADS, K2_SMEM>>>(W_hh, b_hh);
    k3_head<<<256, K3_THREADS, K3_SMEM>>>(edge, gat_W, att_src, att_dst, gat_b,
                                          W1, b1, W2, b2, actW, actb, crW, crb, out);
}